// round 7
// baseline (speedup 1.0000x reference)
#include <cuda_runtime.h>
#include <cstdint>

// RoiAlign (crop_and_resize, bilinear, extrapolation=0) with 2-level FPN select.
// feat0: [2,256,256,256] f32, feat1: [2,128,128,256] f32, rois: [2,512,5] f32
// out:   [2,512,7,7,256] f32
//
// Mapping: one WARP per pooled cell; each lane handles 8 channels (2x float4).
// 8 warps (8 cells) per 256-thread block. All addressing in 32-bit float4 units.

#define NUM_B 2
#define NUM_R 512
#define CCH 256
#define POOL 7
#define CELLS_PER_BOX (POOL * POOL)
#define INV_IMG (1.0f / 1024.0f)
#define LVL_THRESH 48.0f

__device__ __forceinline__ float4 lerp4(float4 a, float4 b, float w) {
    return make_float4(fmaf(b.x - a.x, w, a.x),
                       fmaf(b.y - a.y, w, a.y),
                       fmaf(b.z - a.z, w, a.z),
                       fmaf(b.w - a.w, w, a.w));
}

__global__ __launch_bounds__(256) void roialign_kernel(
    const float4* __restrict__ feat0,
    const float4* __restrict__ feat1,
    const float* __restrict__ rois,
    float4* __restrict__ out,
    int n_cells)
{
    const int warpId = threadIdx.x >> 5;
    const int lane   = threadIdx.x & 31;
    const int cell   = blockIdx.x * 8 + warpId;
    if (cell >= n_cells) return;

    const int box = cell / CELLS_PER_BOX;             // const-div -> mul/shift
    const int pq  = cell - box * CELLS_PER_BOX;       // 0..48
    const int py  = pq / POOL;
    const int px  = pq - py * POOL;
    const int b   = box >> 9;                         // box / 512

    const float* roi = rois + box * 5;
    const float y1 = roi[0];
    const float x1 = roi[1];
    const float y2 = roi[2];
    const float x2 = roi[3];

    const bool lvl1 = ((y2 - y1) > LVL_THRESH) || ((x2 - x1) > LVL_THRESH);
    const float4* __restrict__ img4 = lvl1 ? feat1 : feat0;
    const int HW = lvl1 ? 128 : 256;                  // H == W at both levels
    const float HWm1 = (float)(HW - 1);

    const float ry = (float)py * (1.0f / 6.0f);
    const float rx = (float)px * (1.0f / 6.0f);
    const float ys = (y1 * INV_IMG + ry * (y2 - y1) * INV_IMG) * HWm1;
    const float xs = (x1 * INV_IMG + rx * (x2 - x1) * INV_IMG) * HWm1;

    // out: cell * 64 float4s, lane covers [lane*2, lane*2+1]
    float4* outp = out + cell * (CCH / 4) + lane * 2;

    const bool valid = (ys >= 0.0f) && (ys <= HWm1) &&
                       (xs >= 0.0f) && (xs <= HWm1);
    if (!valid) {
        const float4 z = make_float4(0.f, 0.f, 0.f, 0.f);
        outp[0] = z;
        outp[1] = z;
        return;
    }

    const float y0f = floorf(ys);
    const float x0f = floorf(xs);
    const float wy = ys - y0f;
    const float wx = xs - x0f;

    // valid => y0f,x0f already in [0, HW-1]; only far corner needs clamping
    const int iy0 = (int)y0f;
    const int ix0 = (int)x0f;
    const int iyp = min(iy0 + 1, HW - 1);
    const int ixp = min(ix0 + 1, HW - 1);

    // 32-bit offsets in float4 units (max 4.19M*2 < 2^31)
    const int base00 = ((b * HW + iy0) * HW + ix0) * (CCH / 4);
    const int dx = (ixp - ix0) * (CCH / 4);
    const int dy = (iyp - iy0) * HW * (CCH / 4);

    const float4* p = img4 + base00 + lane * 2;
    const float4 a00 = p[0];
    const float4 b00 = p[1];
    const float4 a01 = p[dx];
    const float4 b01 = p[dx + 1];
    const float4 a10 = p[dy];
    const float4 b10 = p[dy + 1];
    const float4 a11 = p[dy + dx];
    const float4 b11 = p[dy + dx + 1];

    const float4 r0 = lerp4(lerp4(a00, a01, wx), lerp4(a10, a11, wx), wy);
    const float4 r1 = lerp4(lerp4(b00, b01, wx), lerp4(b10, b11, wx), wy);

    outp[0] = r0;
    outp[1] = r1;
}

extern "C" void kernel_launch(void* const* d_in, const int* in_sizes, int n_in,
                              void* d_out, int out_size) {
    const float4* feat0 = (const float4*)d_in[0];
    const float4* feat1 = (const float4*)d_in[1];
    const float* rois   = (const float*)d_in[2];
    float4* out = (float4*)d_out;

    const int n_cells = NUM_B * NUM_R * CELLS_PER_BOX;   // 50176
    const int blocks = (n_cells + 7) / 8;                // 8 cells (warps) per block
    roialign_kernel<<<blocks, 256>>>(feat0, feat1, rois, out, n_cells);
}